// round 1
// baseline (speedup 1.0000x reference)
#include <cuda_runtime.h>
#include <cuda_bf16.h>
#include <cstdint>

#define BB 2
#define CIN 128
#define COUT 64
#define KK 64
#define HWD 16384          // 128*128
#define NPIX (BB*HWD)      // 32768
#define PPB 128            // pixels per gemm block
#define PCHUNK (HWD/PPB)   // 128 gemm blocks per batch

// ---------------- scratch (device globals; no allocation) ----------------
__device__ float g_xt[BB*COUT*HWD];     // xt in [b][o][p] layout (8MB)
__device__ float g_sums[BB*KK*COUT];    // per-bin sums
__device__ float g_cnt[BB*KK];          // per-bin counts
__device__ float g_A[COUT*COUT];        // inv(cov)
__device__ float g_adjm[BB*KK*COUT];    // adj @ means
__device__ float g_csum[COUT];          // BN channel sum
__device__ float g_csq[COUT];           // BN channel sumsq

// ---------------- kernel 0: zero accumulators ----------------
__global__ void k_zero() {
    int t = threadIdx.x;
    for (int i = t; i < BB*KK*COUT; i += blockDim.x) g_sums[i] = 0.f;
    if (t < BB*KK) g_cnt[t] = 0.f;
    if (t < COUT) { g_csum[t] = 0.f; g_csq[t] = 0.f; }
}

// ---------------- kernel 1: GEMM xt = x*Wft + binned sums (+ inverse block) ----------------
__global__ void __launch_bounds__(PPB) k_gemm(const float* __restrict__ x,
                                              const int* __restrict__ idx,
                                              const float* __restrict__ Wft,
                                              const float* __restrict__ Wm) {
    __shared__ float sbuf[64*133];      // 34KB, aliased per path
    __shared__ float prow[128];
    const int tid = threadIdx.x;

    if (blockIdx.x == PCHUNK) {
        // ======== extra block: cov = Wm Wm^T, Gauss-Jordan inverse (SPD, no pivot) ========
        if (blockIdx.y != 0) return;
        // stage Wm padded to 65 for conflict-free reads
        for (int i = tid; i < 64*64; i += PPB) { int r = i >> 6, c = i & 63; sbuf[r*65+c] = Wm[i]; }
        __syncthreads();
        const int i0 = tid & 63, s0 = tid >> 6;   // s0 in {0,1}
        float covr[32];
        #pragma unroll
        for (int jj = 0; jj < 32; jj++) {
            int j = s0*32 + jj;
            float sum = 0.f;
            #pragma unroll 8
            for (int c = 0; c < 64; c++) sum += sbuf[i0*65+c] * sbuf[j*65+c];
            covr[jj] = sum;
        }
        __syncthreads();
        // build augmented [cov | I], stride 133 (conflict-free)
        #pragma unroll
        for (int jj = 0; jj < 32; jj++) sbuf[i0*133 + s0*32 + jj] = covr[jj];
        for (int t = tid; t < 64*64; t += PPB) { int r = t >> 6, c = t & 63; sbuf[r*133 + 64 + c] = (r == c) ? 1.f : 0.f; }
        const int r = tid & 63, sh = tid >> 6;    // thread owns (row r, col-half sh)
        for (int c = 0; c < 64; c++) {
            __syncthreads();
            float d   = sbuf[c*133 + c];
            float inv = 1.0f / d;
            float f   = sbuf[r*133 + c];
            if (tid < 128) prow[tid] = sbuf[c*133 + tid] * inv;
            __syncthreads();
            if (r == c) {
                for (int j = sh*64; j < sh*64 + 64; j++) sbuf[r*133 + j] = prow[j];
            } else {
                for (int j = sh*64; j < sh*64 + 64; j++) sbuf[r*133 + j] -= f * prow[j];
            }
        }
        __syncthreads();
        for (int t = tid; t < 64*64; t += PPB) { int rr = t >> 6, cc = t & 63; g_A[t] = sbuf[rr*133 + 64 + cc]; }
        return;
    }

    // ======== GEMM path ========
    float* sW    = sbuf;             // 4096 floats (64c x 64o chunk)
    float* sBins = sbuf + 4096;      // 64*65 padded bins
    float* sCnt  = sbuf + 4096 + 4160;
    const int b = blockIdx.y;
    const int p = blockIdx.x * PPB + tid;

    for (int i = tid; i < 64*65; i += PPB) sBins[i] = 0.f;
    if (tid < 64) sCnt[tid] = 0.f;

    unsigned long long acc[32];
    #pragma unroll
    for (int i = 0; i < 32; i++) acc[i] = 0ull;

    for (int half = 0; half < 2; half++) {
        __syncthreads();
        for (int i = tid; i < 64*64; i += PPB) sW[i] = Wft[half*4096 + i];
        __syncthreads();
        const float* xp = x + ((size_t)(b*CIN + half*64)) * HWD + p;
        #pragma unroll 8
        for (int c = 0; c < 64; c++) {
            float xv = __ldg(xp + (size_t)c * HWD);
            unsigned long long xx;
            asm("mov.b64 %0, {%1, %1};" : "=l"(xx) : "f"(xv));
            const ulonglong2* wr = reinterpret_cast<const ulonglong2*>(sW + c*64);
            #pragma unroll
            for (int q8 = 0; q8 < 16; q8++) {
                ulonglong2 w = wr[q8];
                asm("fma.rn.f32x2 %0, %1, %2, %0;" : "+l"(acc[2*q8  ]) : "l"(xx), "l"(w.x));
                asm("fma.rn.f32x2 %0, %1, %2, %0;" : "+l"(acc[2*q8+1]) : "l"(xx), "l"(w.y));
            }
        }
    }

    float accf[64];
    #pragma unroll
    for (int i = 0; i < 32; i++)
        asm("mov.b64 {%0, %1}, %2;" : "=f"(accf[2*i]), "=f"(accf[2*i+1]) : "l"(acc[i]));

    // write xt in [b][o][p] layout (coalesced per o)
    float* xtp = g_xt + (size_t)b * COUT * HWD + p;
    #pragma unroll
    for (int o = 0; o < 64; o++) xtp[(size_t)o * HWD] = accf[o];

    // binned scatter via padded shared atomics
    int k = __ldg(idx + b*HWD + p);
    atomicAdd(&sCnt[k], 1.0f);
    float* bk = sBins + k*65;
    #pragma unroll
    for (int o = 0; o < 64; o++) atomicAdd(bk + o, accf[o]);
    __syncthreads();
    float* gs = g_sums + b*KK*COUT;
    for (int i = tid; i < 64*64; i += PPB) {
        int kk2 = i >> 6, oo = i & 63;
        float v = sBins[kk2*65 + oo];
        if (v != 0.f) atomicAdd(gs + i, v);
    }
    if (tid < 64) { float c0 = sCnt[tid]; if (c0 != 0.f) atomicAdd(&g_cnt[b*64 + tid], c0); }
}

// ---------------- kernel 2: adjacency + adj@means per (b,i) ----------------
__global__ void __launch_bounds__(256) k_adj() {
    __shared__ float sMe[64*65];    // means, padded
    __shared__ float sA[64*64];     // inv cov (broadcast reads)
    __shared__ float adjrow[64];
    __shared__ float red[256];
    const int tid = threadIdx.x;
    const int b = blockIdx.x >> 6;
    const int i = blockIdx.x & 63;

    for (int t = tid; t < 64*64; t += 256) {
        int k = t >> 6, o = t & 63;
        float cnt = g_cnt[b*64 + k];
        float den = cnt + (cnt == 0.f ? 1.f : 0.f);
        sMe[k*65 + o] = g_sums[b*4096 + t] / den;
        sA[t] = g_A[t];
    }
    __syncthreads();

    const int j = tid & 63, s = tid >> 6;   // thread: column j, c-slice s (16 c's each)
    float dreg[64];
    #pragma unroll
    for (int d = 0; d < 64; d++) dreg[d] = sMe[i*65 + d] - sMe[j*65 + d];
    float q = 0.f;
    for (int c = s*16; c < s*16 + 16; c++) {
        float w = 0.f;
        const float4* ar = reinterpret_cast<const float4*>(sA + c*64);
        #pragma unroll
        for (int d4 = 0; d4 < 16; d4++) {
            float4 a = ar[d4];
            w += a.x*dreg[4*d4] + a.y*dreg[4*d4+1] + a.z*dreg[4*d4+2] + a.w*dreg[4*d4+3];
        }
        q += dreg[c] * w;
    }
    red[tid] = q;
    __syncthreads();
    if (tid < 64) {
        float qt = red[tid] + red[64 + tid] + red[128 + tid] + red[192 + tid];
        float dist = (tid == i) ? 1e-6f : sqrtf(fmaxf(qt, 1e-12f));
        adjrow[tid] = expf(-dist);
    }
    __syncthreads();
    // adj_means[b,i,o] = sum_j adjrow[j] * means[b,j,o]
    const int o = tid & 63;
    float part = 0.f;
    for (int jj = s*16; jj < s*16 + 16; jj++) part += adjrow[jj] * sMe[jj*65 + o];
    red[tid] = part;
    __syncthreads();
    if (tid < 64)
        g_adjm[b*4096 + i*64 + tid] = red[tid] + red[64 + tid] + red[128 + tid] + red[192 + tid];
}

// ---------------- kernel 3: BN statistics (per-channel sum/sumsq of features) ----------------
__global__ void __launch_bounds__(256) k_stats(const int* __restrict__ idx) {
    const int tid = threadIdx.x;
    const int o = blockIdx.y, b = blockIdx.z;
    const float* xtp = g_xt + (size_t)(b*COUT + o) * HWD;
    const int* ip = idx + b*HWD;
    const float* am = g_adjm + b*4096 + o;
    int p0 = blockIdx.x * 2048 + tid;
    float s = 0.f, sq = 0.f;
    #pragma unroll
    for (int it = 0; it < 8; it++) {
        int p = p0 + it*256;
        int k = __ldg(ip + p);
        float f = xtp[p] + __ldg(am + k*64);
        f = fmaxf(f, 0.f);
        s += f; sq += f*f;
    }
    #pragma unroll
    for (int off = 16; off; off >>= 1) {
        s  += __shfl_down_sync(0xffffffffu, s, off);
        sq += __shfl_down_sync(0xffffffffu, sq, off);
    }
    __shared__ float rs[8], rq[8];
    if ((tid & 31) == 0) { rs[tid >> 5] = s; rq[tid >> 5] = sq; }
    __syncthreads();
    if (tid == 0) {
        float S = 0.f, Q = 0.f;
        #pragma unroll
        for (int w = 0; w < 8; w++) { S += rs[w]; Q += rq[w]; }
        atomicAdd(&g_csum[o], S);
        atomicAdd(&g_csq[o], Q);
    }
}

// ---------------- kernel 4: normalize + write output (B,COUT,H,W) ----------------
__global__ void __launch_bounds__(256) k_out(const int* __restrict__ idx,
                                             const float* __restrict__ gamma,
                                             const float* __restrict__ beta,
                                             float* __restrict__ out) {
    const int tid = threadIdx.x;
    const int o = blockIdx.y, b = blockIdx.z;
    __shared__ float sc, shf;
    if (tid == 0) {
        const float invN = 1.0f / (float)NPIX;
        float mean = g_csum[o] * invN;
        float var  = g_csq[o] * invN - mean * mean;
        float inv  = 1.0f / sqrtf(var + 1e-5f);
        float g = __ldg(gamma + o), be = __ldg(beta + o);
        sc  = g * inv;
        shf = be - mean * g * inv;
    }
    __syncthreads();
    const float* xtp = g_xt + (size_t)(b*COUT + o) * HWD;
    const int* ip = idx + b*HWD;
    const float* am = g_adjm + b*4096 + o;
    float* op = out + (size_t)(b*COUT + o) * HWD;
    int p0 = blockIdx.x * 2048 + tid;
    #pragma unroll
    for (int it = 0; it < 8; it++) {
        int p = p0 + it*256;
        int k = __ldg(ip + p);
        float f = fmaxf(xtp[p] + __ldg(am + k*64), 0.f);
        op[p] = f * sc + shf;
    }
}

// ---------------- launch ----------------
extern "C" void kernel_launch(void* const* d_in, const int* in_sizes, int n_in,
                              void* d_out, int out_size) {
    const float* x     = (const float*)d_in[0];
    const int*   idx   = (const int*)  d_in[1];
    const float* Wft   = (const float*)d_in[2];
    const float* Wm    = (const float*)d_in[3];
    const float* gamma = (const float*)d_in[4];
    const float* beta  = (const float*)d_in[5];
    float* out = (float*)d_out;

    k_zero<<<1, 256>>>();
    k_gemm<<<dim3(PCHUNK + 1, BB), PPB>>>(x, idx, Wft, Wm);
    k_adj<<<BB*KK, 256>>>();
    k_stats<<<dim3(8, COUT, BB), 256>>>(idx);
    k_out<<<dim3(8, COUT, BB), 256>>>(idx, gamma, beta, out);
}

// round 2
// speedup vs baseline: 1.4317x; 1.4317x over previous
#include <cuda_runtime.h>
#include <cuda_bf16.h>
#include <cstdint>

#define BB 2
#define CIN 128
#define COUT 64
#define KK 64
#define HWD 16384          // 128*128
#define NPIX (BB*HWD)      // 32768
#define GPX 128            // pixels per gemm block
#define NGB (NPIX/GPX)     // 256 gemm blocks

// ---------------- scratch (device globals; no allocation) ----------------
__device__ float g_xt[BB*COUT*HWD];     // xt in [b][o][p] layout (8MB)
__device__ float g_sums[BB*KK*COUT];    // per-bin sums
__device__ float g_cnt[BB*KK];          // per-bin counts
__device__ float g_A[COUT*COUT];        // inv(cov)
__device__ float g_adjm[BB*KK*COUT];    // adj @ means, [b][i][o]
__device__ float g_csum[COUT];          // BN channel sum
__device__ float g_csq[COUT];           // BN channel sumsq

// shared layout offsets (floats)
#define SH_X    0        // 32*128 = 4096
#define SH_W    4096     // 32*64  = 2048
#define SH_BINS 6144     // 64*65  = 4160
#define SH_CNT  10304    // 64
#define SH_IDX  10368    // 128
#define SH_TOT  10496

// ---------------- kernel 0: zero accumulators ----------------
__global__ void k_zero() {
    int t = threadIdx.x;
    for (int i = t; i < BB*KK*COUT; i += blockDim.x) g_sums[i] = 0.f;
    if (t < BB*KK) g_cnt[t] = 0.f;
    if (t < COUT) { g_csum[t] = 0.f; g_csq[t] = 0.f; }
}

// ---------------- kernel 1: GEMM xt = x*Wft + binned sums (+ inverse block) ----------------
__global__ void __launch_bounds__(256) k_gemm(const float* __restrict__ x,
                                              const int* __restrict__ idx,
                                              const float* __restrict__ Wft,
                                              const float* __restrict__ Wm) {
    __shared__ float sbuf[SH_TOT];
    __shared__ float prow[128];
    const int tid = threadIdx.x;

    if (blockIdx.x == NGB) {
        // ======== extra block: cov = Wm Wm^T, Gauss-Jordan inverse (SPD, no pivot) ========
        for (int i = tid; i < 64*64; i += 256) { int r = i >> 6, c = i & 63; sbuf[r*65+c] = Wm[i]; }
        __syncthreads();
        const int i0 = tid & 63, s0 = (tid >> 6) & 1;
        float covr[32];
        if (tid < 128) {
            #pragma unroll
            for (int jj = 0; jj < 32; jj++) {
                int j = s0*32 + jj;
                float sum = 0.f;
                #pragma unroll 8
                for (int c = 0; c < 64; c++) sum += sbuf[i0*65+c] * sbuf[j*65+c];
                covr[jj] = sum;
            }
        }
        __syncthreads();
        if (tid < 128) {
            #pragma unroll
            for (int jj = 0; jj < 32; jj++) sbuf[i0*133 + s0*32 + jj] = covr[jj];
        }
        for (int t = tid; t < 64*64; t += 256) { int r = t >> 6, c = t & 63; sbuf[r*133 + 64 + c] = (r == c) ? 1.f : 0.f; }
        const int r = tid & 63, sh = (tid >> 6) & 1;
        for (int c = 0; c < 64; c++) {
            __syncthreads();
            float d   = sbuf[c*133 + c];
            float inv = 1.0f / d;
            float f   = sbuf[r*133 + c];
            if (tid < 128) prow[tid] = sbuf[c*133 + tid] * inv;
            __syncthreads();
            if (tid < 128) {
                if (r == c) {
                    for (int j = sh*64; j < sh*64 + 64; j++) sbuf[r*133 + j] = prow[j];
                } else {
                    for (int j = sh*64; j < sh*64 + 64; j++) sbuf[r*133 + j] -= f * prow[j];
                }
            }
        }
        __syncthreads();
        for (int t = tid; t < 64*64; t += 256) { int rr = t >> 6, cc = t & 63; g_A[t] = sbuf[rr*133 + 64 + cc]; }
        return;
    }

    // ======== GEMM path ========
    // thread tile: 2 pixels (pair) x 16 outputs (group), accumulated as f32x2 over output pairs
    const int group = tid & 3;           // 0..3 -> outs [group*16, group*16+16)
    const int pair  = tid >> 2;          // 0..63 -> pixels 2*pair, 2*pair+1
    const int GP = blockIdx.x * GPX;     // global pixel base
    const int b  = GP >> 14;
    const int P0 = GP & (HWD - 1);

    float* sX    = sbuf + SH_X;
    float* sW    = sbuf + SH_W;
    float* sBins = sbuf + SH_BINS;
    float* sCnt  = sbuf + SH_CNT;
    float* sIdx  = sbuf + SH_IDX;

    // zero bins + stage idx (synced by first chunk barrier)
    for (int i = tid; i < 64*65; i += 256) sBins[i] = 0.f;
    if (tid < 64) sCnt[tid] = 0.f;
    if (tid < 128) sIdx[tid] = (float)__ldg(idx + b*HWD + P0 + tid);

    unsigned long long a0[8], a1[8];     // a0: pixel0, a1: pixel1; each f32x2 = (out 2j, out 2j+1)
    #pragma unroll
    for (int j = 0; j < 8; j++) { a0[j] = 0ull; a1[j] = 0ull; }

    const int rot = group >> 1;          // bank-conflict rotation for W loads

    for (int ch = 0; ch < 4; ch++) {
        __syncthreads();
        // stage W chunk: 32 c x 64 o
        const float4* wsrc = reinterpret_cast<const float4*>(Wft + ch*32*64);
        reinterpret_cast<float4*>(sW)[tid]       = wsrc[tid];
        reinterpret_cast<float4*>(sW)[tid + 256] = wsrc[tid + 256];
        // stage X chunk: 32 c x 128 px
        const float* xbase = x + ((size_t)(b*CIN + ch*32)) * HWD + P0;
        #pragma unroll
        for (int t = 0; t < 4; t++) {
            int q = tid + t*256;
            int r = q >> 5, c4 = q & 31;
            reinterpret_cast<float4*>(sX + r*128)[c4] =
                *reinterpret_cast<const float4*>(xbase + (size_t)r * HWD + c4*4);
        }
        __syncthreads();

        #pragma unroll 2
        for (int cc = 0; cc < 32; cc++) {
            float2 xp = *reinterpret_cast<const float2*>(sX + cc*128 + pair*2);
            unsigned long long xd0, xd1;
            asm("mov.b64 %0, {%1, %1};" : "=l"(xd0) : "f"(xp.x));
            asm("mov.b64 %0, {%1, %1};" : "=l"(xd1) : "f"(xp.y));
            const ulonglong2* wr = reinterpret_cast<const ulonglong2*>(sW + cc*64 + group*16);
            unsigned long long wv[8];
            #pragma unroll
            for (int i = 0; i < 4; i++) {
                int ii = (i + rot) & 3;
                ulonglong2 w = wr[ii];
                wv[ii*2] = w.x; wv[ii*2+1] = w.y;
            }
            #pragma unroll
            for (int j = 0; j < 8; j++) {
                asm("fma.rn.f32x2 %0, %1, %2, %0;" : "+l"(a0[j]) : "l"(xd0), "l"(wv[j]));
                asm("fma.rn.f32x2 %0, %1, %2, %0;" : "+l"(a1[j]) : "l"(xd1), "l"(wv[j]));
            }
        }
    }

    // unpack, write xt as float2 (pixel pair per out), scatter into bins
    const int k0 = (int)sIdx[pair*2];
    const int k1 = (int)sIdx[pair*2 + 1];
    if (group == 0) {
        atomicAdd(&sCnt[k0], 1.0f);
        atomicAdd(&sCnt[k1], 1.0f);
    }
    float* xtb = g_xt + (size_t)b * COUT * HWD + P0 + pair*2;
    #pragma unroll
    for (int j = 0; j < 8; j++) {
        float p0a, p0b, p1a, p1b;
        asm("mov.b64 {%0, %1}, %2;" : "=f"(p0a), "=f"(p0b) : "l"(a0[j]));
        asm("mov.b64 {%0, %1}, %2;" : "=f"(p1a), "=f"(p1b) : "l"(a1[j]));
        int oA = group*16 + 2*j, oB = oA + 1;
        *reinterpret_cast<float2*>(xtb + (size_t)oA * HWD) = make_float2(p0a, p1a);
        *reinterpret_cast<float2*>(xtb + (size_t)oB * HWD) = make_float2(p0b, p1b);
        atomicAdd(&sBins[k0*65 + oA], p0a);
        atomicAdd(&sBins[k0*65 + oB], p0b);
        atomicAdd(&sBins[k1*65 + oA], p1a);
        atomicAdd(&sBins[k1*65 + oB], p1b);
    }
    __syncthreads();
    float* gs = g_sums + b*KK*COUT;
    for (int i = tid; i < 64*64; i += 256) {
        int kk2 = i >> 6, oo = i & 63;
        float v = sBins[kk2*65 + oo];
        if (v != 0.f) atomicAdd(gs + i, v);
    }
    if (tid < 64) { float c0 = sCnt[tid]; if (c0 != 0.f) atomicAdd(&g_cnt[b*64 + tid], c0); }
}

// ---------------- kernel 2: adjacency + adj@means per (b,i) ----------------
__global__ void __launch_bounds__(256) k_adj() {
    __shared__ float sMe[64*65];    // means, padded
    __shared__ float sA[64*64];     // inv cov (broadcast reads)
    __shared__ float adjrow[64];
    __shared__ float red[256];
    const int tid = threadIdx.x;
    const int b = blockIdx.x >> 6;
    const int i = blockIdx.x & 63;

    for (int t = tid; t < 64*64; t += 256) {
        int k = t >> 6, o = t & 63;
        float cnt = g_cnt[b*64 + k];
        float den = cnt + (cnt == 0.f ? 1.f : 0.f);
        sMe[k*65 + o] = g_sums[b*4096 + t] / den;
        sA[t] = g_A[t];
    }
    __syncthreads();

    const int j = tid & 63, s = tid >> 6;   // thread: column j, c-slice s (16 c's each)
    float dreg[64];
    #pragma unroll
    for (int d = 0; d < 64; d++) dreg[d] = sMe[i*65 + d] - sMe[j*65 + d];
    float q = 0.f;
    for (int c = s*16; c < s*16 + 16; c++) {
        float w = 0.f;
        const float4* ar = reinterpret_cast<const float4*>(sA + c*64);
        #pragma unroll
        for (int d4 = 0; d4 < 16; d4++) {
            float4 a = ar[d4];
            w += a.x*dreg[4*d4] + a.y*dreg[4*d4+1] + a.z*dreg[4*d4+2] + a.w*dreg[4*d4+3];
        }
        q += dreg[c] * w;
    }
    red[tid] = q;
    __syncthreads();
    if (tid < 64) {
        float qt = red[tid] + red[64 + tid] + red[128 + tid] + red[192 + tid];
        float dist = (tid == i) ? 1e-6f : sqrtf(fmaxf(qt, 1e-12f));
        adjrow[tid] = expf(-dist);
    }
    __syncthreads();
    const int o = tid & 63;
    float part = 0.f;
    for (int jj = s*16; jj < s*16 + 16; jj++) part += adjrow[jj] * sMe[jj*65 + o];
    red[tid] = part;
    __syncthreads();
    if (tid < 64)
        g_adjm[b*4096 + i*64 + tid] = red[tid] + red[64 + tid] + red[128 + tid] + red[192 + tid];
}

// ---------------- kernel 3: BN statistics ----------------
__global__ void __launch_bounds__(256) k_stats(const int* __restrict__ idx) {
    __shared__ float sAm[64];
    const int tid = threadIdx.x;
    const int o = blockIdx.y, b = blockIdx.z;
    if (tid < 64) sAm[tid] = g_adjm[b*4096 + tid*64 + o];
    __syncthreads();
    const float* xtp = g_xt + (size_t)(b*COUT + o) * HWD;
    const int* ip = idx + b*HWD;
    int p0 = blockIdx.x * 2048 + tid;
    float s = 0.f, sq = 0.f;
    #pragma unroll
    for (int it = 0; it < 8; it++) {
        int p = p0 + it*256;
        int k = __ldg(ip + p);
        float f = fmaxf(xtp[p] + sAm[k], 0.f);
        s += f; sq += f*f;
    }
    #pragma unroll
    for (int off = 16; off; off >>= 1) {
        s  += __shfl_down_sync(0xffffffffu, s, off);
        sq += __shfl_down_sync(0xffffffffu, sq, off);
    }
    __shared__ float rs[8], rq[8];
    if ((tid & 31) == 0) { rs[tid >> 5] = s; rq[tid >> 5] = sq; }
    __syncthreads();
    if (tid == 0) {
        float S = 0.f, Q = 0.f;
        #pragma unroll
        for (int w = 0; w < 8; w++) { S += rs[w]; Q += rq[w]; }
        atomicAdd(&g_csum[o], S);
        atomicAdd(&g_csq[o], Q);
    }
}

// ---------------- kernel 4: normalize + write output ----------------
__global__ void __launch_bounds__(256) k_out(const int* __restrict__ idx,
                                             const float* __restrict__ gamma,
                                             const float* __restrict__ beta,
                                             float* __restrict__ out) {
    __shared__ float sAm[64];
    __shared__ float sc, shf;
    const int tid = threadIdx.x;
    const int o = blockIdx.y, b = blockIdx.z;
    if (tid < 64) sAm[tid] = g_adjm[b*4096 + tid*64 + o];
    if (tid == 0) {
        const float invN = 1.0f / (float)NPIX;
        float mean = g_csum[o] * invN;
        float var  = g_csq[o] * invN - mean * mean;
        float inv  = 1.0f / sqrtf(var + 1e-5f);
        float g = __ldg(gamma + o), be = __ldg(beta + o);
        sc  = g * inv;
        shf = be - mean * g * inv;
    }
    __syncthreads();
    const float* xtp = g_xt + (size_t)(b*COUT + o) * HWD;
    const int* ip = idx + b*HWD;
    float* op = out + (size_t)(b*COUT + o) * HWD;
    int p0 = blockIdx.x * 2048 + tid;
    #pragma unroll
    for (int it = 0; it < 8; it++) {
        int p = p0 + it*256;
        int k = __ldg(ip + p);
        float f = fmaxf(xtp[p] + sAm[k], 0.f);
        op[p] = f * sc + shf;
    }
}

// ---------------- launch ----------------
extern "C" void kernel_launch(void* const* d_in, const int* in_sizes, int n_in,
                              void* d_out, int out_size) {
    const float* x     = (const float*)d_in[0];
    const int*   idx   = (const int*)  d_in[1];
    const float* Wft   = (const float*)d_in[2];
    const float* Wm    = (const float*)d_in[3];
    const float* gamma = (const float*)d_in[4];
    const float* beta  = (const float*)d_in[5];
    float* out = (float*)d_out;

    k_zero<<<1, 256>>>();
    k_gemm<<<NGB + 1, 256>>>(x, idx, Wft, Wm);
    k_adj<<<BB*KK, 256>>>();
    k_stats<<<dim3(8, COUT, BB), 256>>>(idx);
    k_out<<<dim3(8, COUT, BB), 256>>>(idx, gamma, beta, out);
}

// round 3
// speedup vs baseline: 3.0317x; 2.1176x over previous
#include <cuda_runtime.h>
#include <cuda_bf16.h>
#include <cstdint>

#define BB 2
#define CIN 128
#define COUT 64
#define KK 64
#define HWD 16384          // 128*128
#define NPIX (BB*HWD)      // 32768
#define GPX 256            // pixels per gemm block
#define NGB (NPIX/GPX)     // 128 gemm blocks

// ---------------- scratch (device globals; no allocation) ----------------
__device__ float g_xt[BB*COUT*HWD];     // xt in [b][o][p] layout (8MB)
__device__ float g_sums[BB*KK*COUT];    // per-bin sums [b][k][o]
__device__ float g_cnt[BB*KK];          // per-bin counts
__device__ float g_A[COUT*COUT];        // inv(cov)
__device__ float g_adjmT[BB*KK*COUT];   // adj @ means, TRANSPOSED [b][o][i]
__device__ float g_psum[8*COUT];        // BN partial sums  [(b*4+cx)][o]
__device__ float g_psq[8*COUT];         // BN partial sumsq

// ---------------- kernel 1: GEMM xt = x*Wft  (+ inverse in extra block) ----------------
__global__ void __launch_bounds__(512) k_gemm(const float* __restrict__ x,
                                              const float* __restrict__ Wft,
                                              const float* __restrict__ Wm) {
    __shared__ float sbuf[10240];   // gemm: sX[8192] + sW[2048]; GJ: aug[64*133=8512]
    __shared__ float prow[128];
    __shared__ float fcol[64];
    const int tid = threadIdx.x;

    if (blockIdx.x == NGB) {
        // ======== cov = Wm Wm^T, Gauss-Jordan inverse (SPD, no pivot) ========
        for (int i = tid; i < 64*64; i += 512) { int r = i >> 6, c = i & 63; sbuf[r*65+c] = Wm[i]; }
        __syncthreads();
        const int i0 = tid & 63, jg = tid >> 6;   // row i0, j-group of 8
        float cv[8];
        #pragma unroll
        for (int jj = 0; jj < 8; jj++) {
            int j = jg*8 + jj;
            float sum = 0.f;
            #pragma unroll 8
            for (int c = 0; c < 64; c++) sum += sbuf[i0*65+c] * sbuf[j*65+c];
            cv[jj] = sum;
        }
        __syncthreads();
        // build augmented [cov | I], stride 133
        #pragma unroll
        for (int jj = 0; jj < 8; jj++) sbuf[i0*133 + jg*8 + jj] = cv[jj];
        for (int t = tid; t < 64*64; t += 512) { int r = t >> 6, c = t & 63; sbuf[r*133 + 64 + c] = (r == c) ? 1.f : 0.f; }
        const int r = tid & 63, part = tid >> 6;   // row r, 16-col slice
        for (int c = 0; c < 64; c++) {
            __syncthreads();
            if (tid < 128)            prow[tid]      = sbuf[c*133 + tid] * (1.0f / sbuf[c*133 + c]);
            else if (tid < 192)       fcol[tid-128]  = sbuf[(tid-128)*133 + c];
            __syncthreads();
            float f = fcol[r];
            if (r == c) {
                for (int j = part*16; j < part*16 + 16; j++) sbuf[r*133 + j] = prow[j];
            } else {
                for (int j = part*16; j < part*16 + 16; j++) sbuf[r*133 + j] -= f * prow[j];
            }
        }
        __syncthreads();
        for (int t = tid; t < 64*64; t += 512) { int rr = t >> 6, cc = t & 63; g_A[t] = sbuf[rr*133 + 64 + cc]; }
        return;
    }

    // ======== GEMM: 256 px x 64 outs per block; thread tile 4px x 8outs ========
    float* sX = sbuf;            // 32 c x 256 px
    float* sW = sbuf + 8192;     // 32 c x 64 o
    float4* sX4 = reinterpret_cast<float4*>(sX);
    float4* sW4 = reinterpret_cast<float4*>(sW);
    const int GP = blockIdx.x * GPX;
    const int b  = GP >> 14;
    const int P0 = GP & (HWD - 1);
    const int quad = tid & 63;        // pixel quad: px = quad*4..quad*4+3
    const int og   = tid >> 6;        // out group: o = og*8..og*8+7

    float a[4][8];
    #pragma unroll
    for (int p = 0; p < 4; p++)
        #pragma unroll
        for (int o = 0; o < 8; o++) a[p][o] = 0.f;

    for (int ch = 0; ch < 4; ch++) {
        __syncthreads();
        sW4[tid] = reinterpret_cast<const float4*>(Wft)[ch*512 + tid];
        const float* xbase = x + ((size_t)(b*CIN + ch*32)) * HWD + P0;
        #pragma unroll
        for (int t = 0; t < 4; t++) {
            int q = tid + t*512;
            int r = q >> 6, c4 = q & 63;
            sX4[r*64 + c4] = *reinterpret_cast<const float4*>(xbase + (size_t)r * HWD + c4*4);
        }
        __syncthreads();

        #pragma unroll 4
        for (int cc = 0; cc < 32; cc++) {
            float4 xv = sX4[cc*64 + quad];
            float4 w0 = sW4[cc*16 + og*2];
            float4 w1 = sW4[cc*16 + og*2 + 1];
            const float xs[4] = {xv.x, xv.y, xv.z, xv.w};
            const float ws[8] = {w0.x, w0.y, w0.z, w0.w, w1.x, w1.y, w1.z, w1.w};
            #pragma unroll
            for (int p = 0; p < 4; p++)
                #pragma unroll
                for (int o = 0; o < 8; o++) a[p][o] += xs[p] * ws[o];
        }
    }

    // epilogue: coalesced float4 stores, xt[b][o][p]
    float* xtb = g_xt + (size_t)b * COUT * HWD + P0 + quad*4;
    #pragma unroll
    for (int oo = 0; oo < 8; oo++) {
        int o = og*8 + oo;
        *reinterpret_cast<float4*>(xtb + (size_t)o * HWD) =
            make_float4(a[0][oo], a[1][oo], a[2][oo], a[3][oo]);
    }
}

// ---------------- kernel 2: per-bin sums (atomic-free, lane-private bins) ----------------
__global__ void __launch_bounds__(128) k_sums(const int* __restrict__ idx) {
    __shared__ float sb[64*129];    // bin k at sb[k*129 + tid]
    const int tid = threadIdx.x;
    const int o = blockIdx.x, b = blockIdx.y;
    for (int i = tid; i < 64*129; i += 128) sb[i] = 0.f;
    __syncthreads();
    const float* xtp = g_xt + (size_t)(b*COUT + o) * HWD;
    const int* ip = idx + b*HWD;
    for (int p = tid; p < HWD; p += 128) {
        int k = __ldg(ip + p);
        sb[k*129 + tid] += xtp[p];
    }
    __syncthreads();
    // reduce: thread t handles half (t&1) of bin k = t>>1
    {
        int k = tid >> 1, half = tid & 1;
        float s = 0.f;
        const float* row = sb + k*129 + half*64;
        #pragma unroll 8
        for (int m = 0; m < 64; m++) s += row[m];
        s += __shfl_xor_sync(0xffffffffu, s, 1);
        if (half == 0) g_sums[b*4096 + k*64 + o] = s;
    }
    // counts (one o-block per batch does it)
    if (o == 0) {
        __syncthreads();
        for (int i = tid; i < 64*129; i += 128) sb[i] = 0.f;
        __syncthreads();
        for (int p = tid; p < HWD; p += 128) {
            int k = __ldg(ip + p);
            sb[k*129 + tid] += 1.0f;
        }
        __syncthreads();
        int k = tid >> 1, half = tid & 1;
        float s = 0.f;
        const float* row = sb + k*129 + half*64;
        #pragma unroll 8
        for (int m = 0; m < 64; m++) s += row[m];
        s += __shfl_xor_sync(0xffffffffu, s, 1);
        if (half == 0) g_cnt[b*64 + k] = s;
    }
}

// ---------------- kernel 3: adjacency + adj@means per (b,i) ----------------
__global__ void __launch_bounds__(256) k_adj() {
    __shared__ float sMe[64*65];    // means, padded
    __shared__ float sA[64*64];     // inv cov
    __shared__ float adjrow[64];
    __shared__ float red[256];
    const int tid = threadIdx.x;
    const int b = blockIdx.x >> 6;
    const int i = blockIdx.x & 63;

    for (int t = tid; t < 64*64; t += 256) {
        int k = t >> 6, o = t & 63;
        float cnt = g_cnt[b*64 + k];
        float den = cnt + (cnt == 0.f ? 1.f : 0.f);
        sMe[k*65 + o] = g_sums[b*4096 + t] / den;
        sA[t] = g_A[t];
    }
    __syncthreads();

    const int j = tid & 63, s = tid >> 6;
    float dreg[64];
    #pragma unroll
    for (int d = 0; d < 64; d++) dreg[d] = sMe[i*65 + d] - sMe[j*65 + d];
    float q = 0.f;
    for (int c = s*16; c < s*16 + 16; c++) {
        float w = 0.f;
        const float4* ar = reinterpret_cast<const float4*>(sA + c*64);
        #pragma unroll
        for (int d4 = 0; d4 < 16; d4++) {
            float4 aa = ar[d4];
            w += aa.x*dreg[4*d4] + aa.y*dreg[4*d4+1] + aa.z*dreg[4*d4+2] + aa.w*dreg[4*d4+3];
        }
        q += dreg[c] * w;
    }
    red[tid] = q;
    __syncthreads();
    if (tid < 64) {
        float qt = red[tid] + red[64 + tid] + red[128 + tid] + red[192 + tid];
        float dist = (tid == i) ? 1e-6f : sqrtf(fmaxf(qt, 1e-12f));
        adjrow[tid] = expf(-dist);
    }
    __syncthreads();
    const int o = tid & 63;
    float part = 0.f;
    for (int jj = s*16; jj < s*16 + 16; jj++) part += adjrow[jj] * sMe[jj*65 + o];
    red[tid] = part;
    __syncthreads();
    if (tid < 64)
        g_adjmT[b*4096 + tid*64 + i] = red[tid] + red[64 + tid] + red[128 + tid] + red[192 + tid];
}

// ---------------- kernel 4: BN partial statistics (vectorized) ----------------
__global__ void __launch_bounds__(256) k_stats(const int* __restrict__ idx) {
    __shared__ float sAm[64];
    const int tid = threadIdx.x;
    const int cx = blockIdx.x, o = blockIdx.y, b = blockIdx.z;
    if (tid < 64) sAm[tid] = g_adjmT[b*4096 + o*64 + tid];
    __syncthreads();
    const float4* xt4 = reinterpret_cast<const float4*>(g_xt + (size_t)(b*COUT + o) * HWD);
    const int4*   ip4 = reinterpret_cast<const int4*>(idx + b*HWD);
    int q0 = cx * 1024 + tid;
    float s = 0.f, sq = 0.f;
    #pragma unroll
    for (int it = 0; it < 4; it++) {
        int q = q0 + it*256;
        float4 v = xt4[q];
        int4 kk = __ldg(ip4 + q);
        float f0 = fmaxf(v.x + sAm[kk.x], 0.f);
        float f1 = fmaxf(v.y + sAm[kk.y], 0.f);
        float f2 = fmaxf(v.z + sAm[kk.z], 0.f);
        float f3 = fmaxf(v.w + sAm[kk.w], 0.f);
        s  += f0 + f1 + f2 + f3;
        sq += f0*f0 + f1*f1 + f2*f2 + f3*f3;
    }
    #pragma unroll
    for (int off = 16; off; off >>= 1) {
        s  += __shfl_down_sync(0xffffffffu, s, off);
        sq += __shfl_down_sync(0xffffffffu, sq, off);
    }
    __shared__ float rs[8], rq[8];
    if ((tid & 31) == 0) { rs[tid >> 5] = s; rq[tid >> 5] = sq; }
    __syncthreads();
    if (tid == 0) {
        float S = 0.f, Q = 0.f;
        #pragma unroll
        for (int w = 0; w < 8; w++) { S += rs[w]; Q += rq[w]; }
        g_psum[(b*4 + cx)*COUT + o] = S;
        g_psq [(b*4 + cx)*COUT + o] = Q;
    }
}

// ---------------- kernel 5: normalize + write output (vectorized) ----------------
__global__ void __launch_bounds__(256) k_out(const int* __restrict__ idx,
                                             const float* __restrict__ gamma,
                                             const float* __restrict__ beta,
                                             float* __restrict__ out) {
    __shared__ float sAm[64];
    __shared__ float sc, shf;
    const int tid = threadIdx.x;
    const int cx = blockIdx.x, o = blockIdx.y, b = blockIdx.z;
    if (tid < 64) sAm[tid] = g_adjmT[b*4096 + o*64 + tid];
    if (tid == 0) {
        float S = 0.f, Q = 0.f;
        #pragma unroll
        for (int i = 0; i < 8; i++) { S += g_psum[i*COUT + o]; Q += g_psq[i*COUT + o]; }
        const float invN = 1.0f / (float)NPIX;
        float mean = S * invN;
        float var  = Q * invN - mean * mean;
        float inv  = 1.0f / sqrtf(var + 1e-5f);
        float g = __ldg(gamma + o), be = __ldg(beta + o);
        sc  = g * inv;
        shf = be - mean * g * inv;
    }
    __syncthreads();
    const float4* xt4 = reinterpret_cast<const float4*>(g_xt + (size_t)(b*COUT + o) * HWD);
    const int4*   ip4 = reinterpret_cast<const int4*>(idx + b*HWD);
    float4* o4 = reinterpret_cast<float4*>(out + (size_t)(b*COUT + o) * HWD);
    int q0 = cx * 1024 + tid;
    float lsc = sc, lsh = shf;
    #pragma unroll
    for (int it = 0; it < 4; it++) {
        int q = q0 + it*256;
        float4 v = xt4[q];
        int4 kk = __ldg(ip4 + q);
        float4 r;
        r.x = fmaxf(v.x + sAm[kk.x], 0.f) * lsc + lsh;
        r.y = fmaxf(v.y + sAm[kk.y], 0.f) * lsc + lsh;
        r.z = fmaxf(v.z + sAm[kk.z], 0.f) * lsc + lsh;
        r.w = fmaxf(v.w + sAm[kk.w], 0.f) * lsc + lsh;
        o4[q] = r;
    }
}

// ---------------- launch ----------------
extern "C" void kernel_launch(void* const* d_in, const int* in_sizes, int n_in,
                              void* d_out, int out_size) {
    const float* x     = (const float*)d_in[0];
    const int*   idx   = (const int*)  d_in[1];
    const float* Wft   = (const float*)d_in[2];
    const float* Wm    = (const float*)d_in[3];
    const float* gamma = (const float*)d_in[4];
    const float* beta  = (const float*)d_in[5];
    float* out = (float*)d_out;

    k_gemm<<<NGB + 1, 512>>>(x, Wft, Wm);
    k_sums<<<dim3(COUT, BB), 128>>>(idx);
    k_adj<<<BB*KK, 256>>>();
    k_stats<<<dim3(4, COUT, BB), 256>>>(idx);
    k_out<<<dim3(4, COUT, BB), 256>>>(idx, gamma, beta, out);
}